// round 8
// baseline (speedup 1.0000x reference)
#include <cuda_runtime.h>
#include <cstdint>

// ---------------------------------------------------------------------------
// Noise2Void masked-MSE, exact replication of the JAX reference with
// jax.random.key(42) under the PARTITIONABLE threefry scheme (JAX >= 0.5
// default: jax_threefry_partitionable=True).
//
// Loss collapses to hot pixels only:
//   loss = sum_t (x[n,c,ry,rx] - x[n,c,hy,hx])^2 / (N*C*K)
//
// Single fused kernel, 192 blocks x 128 threads (covers all 148 SMs).
// Hot-pixel load is issued before the uniform threefry to hide DRAM latency.
// Last-block-done (threadfence + self-resetting atomicInc) deterministic
// final reduction; CUDA-graph-replay idempotent.
// ---------------------------------------------------------------------------

#define N_  32
#define C_  3
#define H_  512
#define W_  512
#define ITEMS 24576       // N_*C_*256
#define TPB  128
#define NBLK 192          // ITEMS / TPB

__device__ float g_partial[NBLK];
__device__ unsigned int g_count = 0;

__host__ __device__ __forceinline__ uint32_t rotl32(uint32_t v, int r)
{
#ifdef __CUDA_ARCH__
    return __funnelshift_l(v, v, r);
#else
    return (v << r) | (v >> (32 - r));
#endif
}

__host__ __device__ __forceinline__ void threefry2x32(
    uint32_t k0, uint32_t k1, uint32_t x0, uint32_t x1,
    uint32_t &o0, uint32_t &o1)
{
    const uint32_t ks0 = k0, ks1 = k1, ks2 = k0 ^ k1 ^ 0x1BD11BDAu;
    x0 += ks0; x1 += ks1;
#define TF_R4(a,b,c,d)                                   \
    x0 += x1; x1 = rotl32(x1,(a)); x1 ^= x0;             \
    x0 += x1; x1 = rotl32(x1,(b)); x1 ^= x0;             \
    x0 += x1; x1 = rotl32(x1,(c)); x1 ^= x0;             \
    x0 += x1; x1 = rotl32(x1,(d)); x1 ^= x0;
    TF_R4(13,15,26, 6)  x0 += ks1; x1 += ks2 + 1u;
    TF_R4(17,29,16,24)  x0 += ks2; x1 += ks0 + 2u;
    TF_R4(13,15,26, 6)  x0 += ks0; x1 += ks1 + 3u;
    TF_R4(17,29,16,24)  x0 += ks1; x1 += ks2 + 4u;
    TF_R4(13,15,26, 6)  x0 += ks2; x1 += ks0 + 5u;
#undef TF_R4
    o0 = x0; o1 = x1;
}

// partitionable random_bits: 32-bit element i = o0 ^ o1 of block (0, i)
__device__ __forceinline__ uint32_t rb32(uint32_t k0, uint32_t k1, uint32_t i)
{
    uint32_t o0, o1;
    threefry2x32(k0, k1, 0u, i, o0, o1);
    return o0 ^ o1;
}

__device__ __forceinline__ float warp_sum(float v)
{
#pragma unroll
    for (int o = 16; o > 0; o >>= 1)
        v += __shfl_down_sync(0xFFFFFFFFu, v, o);
    return v;
}

__global__ void __launch_bounds__(TPB)
n2v_fused(const float* __restrict__ x, float* __restrict__ out,
          uint32_t kl0, uint32_t kl1,   // randint lower-bits key
          uint32_t ku0, uint32_t ku1)   // uniform key (k2)
{
    const int tid  = threadIdx.x;
    const int lane = tid & 31;
    const int wid  = tid >> 5;
    const int t    = blockIdx.x * TPB + tid;   // item index in [0, ITEMS)

    // --- Phase 1: offset RNG (y, x) -> hot pixel; issue its load early ---
    uint32_t oy = rb32(kl0, kl1, (uint32_t)(2 * t));
    uint32_t ox = rb32(kl0, kl1, (uint32_t)(2 * t + 1));

    int nc = t >> 8;            // n*C + c
    int k  = t & 255;
    int by = k >> 4;
    int bx = k & 15;

    int hy = by * 32 + (int)(oy & 31u);
    int hx = bx * 32 + (int)(ox & 31u);

    const float* img = x + (size_t)nc * (H_ * W_);
    float b = __ldg(img + hy * W_ + hx);      // long-scoreboard hidden below

    // ROI bounds (independent of the uniform draw), faithful quirk:
    // roimax = min(hc+3, shape-1)
    int rmin0 = max(hy - 2, 0);
    int rmax0 = min(hy + 3, H_ - 1);
    int rmin1 = max(hx - 2, 0);
    int rmax1 = min(hx + 3, W_ - 1);
    int sh0 = rmax0 - rmin0;
    int sh1 = rmax1 - rmin1;

    bool hasc = (sh0 > 2) && (sh1 > 2);
    int m = sh0 * sh1 - (hasc ? 1 : 0);

    // --- Phase 2: uniform RNG -> replacement pixel ---
    uint32_t ub = rb32(ku0, ku1, (uint32_t)t);

    // uniform in [0,1): bitcast((bits>>9)|0x3f800000) - 1.0
    float uf = __uint_as_float((ub >> 9) | 0x3f800000u) - 1.0f;
    int u = (int)floorf(uf * (float)m);
    u = min(u, m - 1);
    int cflat = 2 * sh1 + 2;                 // flat index of rc=(2,2)
    if (hasc && u >= cflat) u += 1;

    int ry = rmin0 + u / sh1;
    int rx = rmin1 + u % sh1;

    float a = __ldg(img + ry * W_ + rx);
    float d = a - b;

    // ---- block reduction (warp shuffles + one smem hop) ----
    float v = warp_sum(d * d);
    __shared__ float wsum[TPB / 32];
    __shared__ bool is_last;
    if (lane == 0) wsum[wid] = v;
    __syncthreads();
    if (tid == 0) {
        float s = (wsum[0] + wsum[1]) + (wsum[2] + wsum[3]);
        g_partial[blockIdx.x] = s;
        __threadfence();
        unsigned int prev = atomicInc(&g_count, NBLK - 1);  // wraps to 0 at NBLK-1
        is_last = (prev == NBLK - 1);
    }
    __syncthreads();

    // ---- last block performs the deterministic final reduction ----
    if (is_last) {
        // 192 partials, 128 threads: thread i owns partial[i] (+ partial[i+128] for i<64)
        float p = g_partial[tid];
        if (tid < NBLK - TPB) p += g_partial[tid + TPB];
        p = warp_sum(p);
        if (lane == 0) wsum[wid] = p;
        __syncthreads();
        if (tid == 0) {
            float s = (wsum[0] + wsum[1]) + (wsum[2] + wsum[3]);
            out[0] = s / 24576.0f;           // mask.sum() = N*C*K exactly
        }
    }
}

extern "C" void kernel_launch(void* const* d_in, const int* in_sizes, int n_in,
                              void* d_out, int out_size)
{
    (void)in_sizes; (void)n_in; (void)out_size;
    const float* x = (const float*)d_in[0];
    float* out = (float*)d_out;

    // ---- Derive JAX keys on host (pure CPU math, graph-capture safe) ----
    // root = key(42) = (0, 42)
    uint32_t A0, A1, B0, B1;
    // split(root, 2) foldlike: sub-key i = full block threefry(root; 0, i)
    threefry2x32(0u, 42u, 0u, 0u, A0, A1);   // k1 (randint key)
    threefry2x32(0u, 42u, 0u, 1u, B0, B1);   // k2 (uniform key)

    // randint internally splits k1 (foldlike); lower_bits uses the SECOND
    // sub-key = threefry(k1; 0, 1). (higher-bits key unused: (2^16 % 32)^2 % 32 = 0)
    uint32_t kl0, kl1;
    threefry2x32(A0, A1, 0u, 1u, kl0, kl1);

    n2v_fused<<<NBLK, TPB>>>(x, out, kl0, kl1, B0, B1);
}

// round 9
// speedup vs baseline: 1.3077x; 1.3077x over previous
#include <cuda_runtime.h>
#include <cstdint>

// ---------------------------------------------------------------------------
// Noise2Void masked-MSE, exact replication of the JAX reference with
// jax.random.key(42) under the PARTITIONABLE threefry scheme (JAX >= 0.5
// default: jax_threefry_partitionable=True).
//
// Loss collapses to hot pixels only:
//   loss = sum_t (x[n,c,ry,rx] - x[n,c,hy,hx])^2 / (N*C*K)
//
// Single kernel, single packed-integer atomic for the global reduction:
//   g_acc += (1 << 56) | round(block_sum * 2^32)
// Integer adds are associative -> bitwise-deterministic result independent of
// block arrival order. The block seeing prev>>56 == NBLK-1 holds the total
// in-register, writes out[0], and resets g_acc (replay-idempotent).
// ---------------------------------------------------------------------------

#define N_  32
#define C_  3
#define H_  512
#define W_  512
#define ITEMS 24576       // N_*C_*256
#define TPB  256
#define NBLK 96           // ITEMS / TPB

#define CNT_SHIFT 56
#define SUM_MASK  ((1ULL << CNT_SHIFT) - 1ULL)

__device__ unsigned long long g_acc = 0ULL;

__host__ __device__ __forceinline__ uint32_t rotl32(uint32_t v, int r)
{
#ifdef __CUDA_ARCH__
    return __funnelshift_l(v, v, r);
#else
    return (v << r) | (v >> (32 - r));
#endif
}

__host__ __device__ __forceinline__ void threefry2x32(
    uint32_t k0, uint32_t k1, uint32_t x0, uint32_t x1,
    uint32_t &o0, uint32_t &o1)
{
    const uint32_t ks0 = k0, ks1 = k1, ks2 = k0 ^ k1 ^ 0x1BD11BDAu;
    x0 += ks0; x1 += ks1;
#define TF_R4(a,b,c,d)                                   \
    x0 += x1; x1 = rotl32(x1,(a)); x1 ^= x0;             \
    x0 += x1; x1 = rotl32(x1,(b)); x1 ^= x0;             \
    x0 += x1; x1 = rotl32(x1,(c)); x1 ^= x0;             \
    x0 += x1; x1 = rotl32(x1,(d)); x1 ^= x0;
    TF_R4(13,15,26, 6)  x0 += ks1; x1 += ks2 + 1u;
    TF_R4(17,29,16,24)  x0 += ks2; x1 += ks0 + 2u;
    TF_R4(13,15,26, 6)  x0 += ks0; x1 += ks1 + 3u;
    TF_R4(17,29,16,24)  x0 += ks1; x1 += ks2 + 4u;
    TF_R4(13,15,26, 6)  x0 += ks2; x1 += ks0 + 5u;
#undef TF_R4
    o0 = x0; o1 = x1;
}

// partitionable random_bits: 32-bit element i = o0 ^ o1 of block (0, i)
__device__ __forceinline__ uint32_t rb32(uint32_t k0, uint32_t k1, uint32_t i)
{
    uint32_t o0, o1;
    threefry2x32(k0, k1, 0u, i, o0, o1);
    return o0 ^ o1;
}

__device__ __forceinline__ float warp_sum(float v)
{
#pragma unroll
    for (int o = 16; o > 0; o >>= 1)
        v += __shfl_down_sync(0xFFFFFFFFu, v, o);
    return v;
}

__global__ void __launch_bounds__(TPB)
n2v_fused(const float* __restrict__ x, float* __restrict__ out,
          uint32_t kl0, uint32_t kl1,   // randint lower-bits key
          uint32_t ku0, uint32_t ku1)   // uniform key (k2)
{
    const int tid  = threadIdx.x;
    const int lane = tid & 31;
    const int wid  = tid >> 5;
    const int t    = blockIdx.x * TPB + tid;   // item index in [0, ITEMS)

    // --- Phase 1: offset RNG (y, x) -> hot pixel; issue its load early ---
    uint32_t oy = rb32(kl0, kl1, (uint32_t)(2 * t));
    uint32_t ox = rb32(kl0, kl1, (uint32_t)(2 * t + 1));

    int nc = t >> 8;            // n*C + c
    int k  = t & 255;
    int by = k >> 4;
    int bx = k & 15;

    int hy = by * 32 + (int)(oy & 31u);
    int hx = bx * 32 + (int)(ox & 31u);

    const float* img = x + (size_t)nc * (H_ * W_);
    float b = __ldg(img + hy * W_ + hx);      // long-scoreboard hidden below

    // ROI bounds (independent of the uniform draw), faithful quirk:
    // roimax = min(hc+3, shape-1)
    int rmin0 = max(hy - 2, 0);
    int rmax0 = min(hy + 3, H_ - 1);
    int rmin1 = max(hx - 2, 0);
    int rmax1 = min(hx + 3, W_ - 1);
    int sh0 = rmax0 - rmin0;
    int sh1 = rmax1 - rmin1;

    bool hasc = (sh0 > 2) && (sh1 > 2);
    int m = sh0 * sh1 - (hasc ? 1 : 0);

    // --- Phase 2: uniform RNG -> replacement pixel ---
    uint32_t ub = rb32(ku0, ku1, (uint32_t)t);

    // uniform in [0,1): bitcast((bits>>9)|0x3f800000) - 1.0
    float uf = __uint_as_float((ub >> 9) | 0x3f800000u) - 1.0f;
    int u = (int)floorf(uf * (float)m);
    u = min(u, m - 1);
    int cflat = 2 * sh1 + 2;                 // flat index of rc=(2,2)
    if (hasc && u >= cflat) u += 1;

    int ry = rmin0 + u / sh1;
    int rx = rmin1 + u % sh1;

    float a = __ldg(img + ry * W_ + rx);
    float d = a - b;

    // ---- block reduction (deterministic fixed tree) ----
    float v = warp_sum(d * d);
    __shared__ float wsum[TPB / 32];
    if (lane == 0) wsum[wid] = v;
    __syncthreads();

    if (tid == 0) {
        float s = ((wsum[0] + wsum[1]) + (wsum[2] + wsum[3]))
                + ((wsum[4] + wsum[5]) + (wsum[6] + wsum[7]));

        // fixed-point (2^-32) contribution; exact fp32->double->u64 conversion
        unsigned long long contrib =
            (unsigned long long)((double)s * 4294967296.0);
        unsigned long long prev =
            atomicAdd(&g_acc, (1ULL << CNT_SHIFT) + contrib);

        if ((prev >> CNT_SHIFT) == (unsigned long long)(NBLK - 1)) {
            // all other 95 blocks' atomics have completed; total is in-register
            unsigned long long total = ((prev & SUM_MASK) + contrib) & SUM_MASK;
            g_acc = 0ULL;  // reset for next graph replay (race-free: we're last)
            out[0] = (float)((double)total * (1.0 / 4294967296.0) / 24576.0);
        }
    }
}

extern "C" void kernel_launch(void* const* d_in, const int* in_sizes, int n_in,
                              void* d_out, int out_size)
{
    (void)in_sizes; (void)n_in; (void)out_size;
    const float* x = (const float*)d_in[0];
    float* out = (float*)d_out;

    // ---- Derive JAX keys on host (pure CPU math, graph-capture safe) ----
    // root = key(42) = (0, 42)
    uint32_t A0, A1, B0, B1;
    // split(root, 2) foldlike: sub-key i = full block threefry(root; 0, i)
    threefry2x32(0u, 42u, 0u, 0u, A0, A1);   // k1 (randint key)
    threefry2x32(0u, 42u, 0u, 1u, B0, B1);   // k2 (uniform key)

    // randint internally splits k1 (foldlike); lower_bits uses the SECOND
    // sub-key = threefry(k1; 0, 1). (higher-bits key unused: (2^16 % 32)^2 % 32 = 0)
    uint32_t kl0, kl1;
    threefry2x32(A0, A1, 0u, 1u, kl0, kl1);

    n2v_fused<<<NBLK, TPB>>>(x, out, kl0, kl1, B0, B1);
}